// round 12
// baseline (speedup 1.0000x reference)
#include <cuda_runtime.h>
#include <cuda_bf16.h>
#include <math.h>
#include <stdint.h>

#define BDIM 4096
#define DDIM 512
#define MARGIN 0.2f

#define NTILE   32
#define NBLK    (NTILE * (NTILE + 1) / 2)  // 528
#define NITER   (DDIM / 64)                // 8 iterations of BK=64
#define STAGE_BYTES 32768                  // A(16K) + B(16K)
#define DYN_SMEM (3 * STAGE_BYTES)         // 96KB, 3 stages

// ---------------------------------------------------------------------------
__device__ float          g_sq[BDIM];
__device__ float          g_dap[BDIM];
__device__ float          g_dap2[BDIM];
__device__ unsigned int   g_min_sel[BDIM];
__device__ unsigned int   g_min_all[BDIM];
__device__ __nv_bfloat16  g_abf[BDIM * DDIM];

__device__ __forceinline__ uint32_t smem_u32(const void* p) {
    uint32_t a;
    asm("{ .reg .u64 t; cvta.to.shared.u64 t, %1; cvt.u32.u64 %0, t; }" : "=r"(a) : "l"(p));
    return a;
}

// 128B rows (64 bf16), swizzle: chunk (16B) index XOR row&7 -> conflict-free
// ldmatrix (8 consecutive rows, same kc, hit 8 distinct bank groups).
__device__ __forceinline__ uint32_t sw_off(int row, int kc) {
    return (uint32_t)(row * 128 + ((kc ^ (row & 7)) << 4));
}

// ---------------------------------------------------------------------------
// Kernel A: per-row stats + init minima + bf16 conversion. One warp per row.
// ---------------------------------------------------------------------------
__global__ __launch_bounds__(512)
void row_stats_kernel(const float* __restrict__ anchor,
                      const float* __restrict__ positive) {
    int warp = threadIdx.x >> 5;
    int lane = threadIdx.x & 31;
    int row  = blockIdx.x * 16 + warp;
    const float* a = anchor   + (size_t)row * DDIM;
    const float* p = positive + (size_t)row * DDIM;

    float s_sq = 0.f, s_ap = 0.f;
#pragma unroll
    for (int c = lane * 4; c < DDIM; c += 128) {
        float4 av = *reinterpret_cast<const float4*>(a + c);
        float4 pv = *reinterpret_cast<const float4*>(p + c);
        s_sq += av.x * av.x + av.y * av.y + av.z * av.z + av.w * av.w;
        float dx = av.x - pv.x, dy = av.y - pv.y, dz = av.z - pv.z, dw = av.w - pv.w;
        s_ap += dx * dx + dy * dy + dz * dz + dw * dw;
        __nv_bfloat162 b0 = __floats2bfloat162_rn(av.x, av.y);
        __nv_bfloat162 b1 = __floats2bfloat162_rn(av.z, av.w);
        uint2 packed = make_uint2(*reinterpret_cast<uint32_t*>(&b0),
                                  *reinterpret_cast<uint32_t*>(&b1));
        *reinterpret_cast<uint2*>(&g_abf[(size_t)row * DDIM + c]) = packed;
    }
#pragma unroll
    for (int m = 16; m > 0; m >>= 1) {
        s_sq += __shfl_xor_sync(0xffffffffu, s_sq, m);
        s_ap += __shfl_xor_sync(0xffffffffu, s_ap, m);
    }
    if (lane == 0) {
        g_sq[row]      = s_sq;
        g_dap[row]     = s_ap;
        g_dap2[row]    = s_ap * s_ap;
        g_min_sel[row] = 0x7F800000u;
        g_min_all[row] = 0x7F800000u;
    }
}

// ---------------------------------------------------------------------------
// Kernel B: symmetric bf16 HMMA Gram tile (128x128x512), upper triangle only,
// fused row+column masked-min epilogue. 256 thr / 8 warps; warp tile 32x64.
// BK=64, 3-stage cp.async ring (96KB), one barrier per iteration.
// ---------------------------------------------------------------------------
__global__ __launch_bounds__(256, 2)
void tile_kernel(const int* __restrict__ labels) {
    extern __shared__ __align__(1024) char dsm[];
    __shared__ float sqj_s[128];
    __shared__ float dpj_s[128];
    __shared__ int   labj_s[128];

    const int tid    = threadIdx.x;
    const int wid    = tid >> 5;
    const int lane   = tid & 31;
    const int warp_m = wid & 3;
    const int warp_n = wid >> 2;

    int t = blockIdx.x;
    int bi = 0;
    {
        int rem = t;
        while (rem >= NTILE - bi) { rem -= NTILE - bi; bi++; }
        t = bi + rem;
    }
    const int bj = t;
    const int i0 = bi * 128;
    const int j0 = bj * 128;

    if (tid < 128) {
        sqj_s[tid]  = g_sq[j0 + tid];
        dpj_s[tid]  = g_dap2[j0 + tid];
        labj_s[tid] = labels[j0 + tid];
    }

    const uint32_t dsm_u = smem_u32(dsm);

    // Fill: thread t loads one full 128B row-chunk: matrix = t>>7, row = t&127.
    const int ld_mat = tid >> 7;          // 0 = A(i-side), 1 = B(j-side)
    const int ld_row = tid & 127;
    const __nv_bfloat16* ld_src =
        g_abf + (size_t)((ld_mat ? j0 : i0) + ld_row) * DDIM;

    auto issue_loads = [&](int stage, int k0) {
        uint32_t sbase = dsm_u + stage * STAGE_BYTES + ld_mat * 16384;
        const __nv_bfloat16* src = ld_src + k0;
#pragma unroll
        for (int kc = 0; kc < 8; kc++) {
            asm volatile("cp.async.cg.shared.global [%0], [%1], 16;"
                         :: "r"(sbase + sw_off(ld_row, kc)), "l"(src + kc * 8) : "memory");
        }
        asm volatile("cp.async.commit_group;" ::: "memory");
    };

    float acc[2][8][4];
#pragma unroll
    for (int mf = 0; mf < 2; mf++)
#pragma unroll
        for (int nf = 0; nf < 8; nf++)
#pragma unroll
            for (int c = 0; c < 4; c++) acc[mf][nf][c] = 0.f;

    issue_loads(0, 0);
    issue_loads(1, 64);

#pragma unroll
    for (int it = 0; it < NITER; it++) {
        const int buf = it % 3;
        if (it < NITER - 1) asm volatile("cp.async.wait_group 1;" ::: "memory");
        else                asm volatile("cp.async.wait_group 0;" ::: "memory");
        // Single barrier: stage (it+2)%3 == stage (it-1)%3; barrier guarantees
        // all warps finished reading it-1 before the refill below.
        __syncthreads();
        if (it + 2 < NITER) issue_loads((it + 2) % 3, (it + 2) * 64);

        const uint32_t a_base = dsm_u + buf * STAGE_BYTES;
        const uint32_t b_base = a_base + 16384;
#pragma unroll
        for (int s = 0; s < 4; s++) {
            const int kc = 2 * s + (lane >> 4);
            uint32_t a[2][4];
#pragma unroll
            for (int mf = 0; mf < 2; mf++) {
                int row = warp_m * 32 + mf * 16 + ((lane >> 3) & 1) * 8 + (lane & 7);
                uint32_t addr = a_base + sw_off(row, kc);
                asm volatile("ldmatrix.sync.aligned.m8n8.x4.shared.b16 {%0,%1,%2,%3}, [%4];"
                             : "=r"(a[mf][0]), "=r"(a[mf][1]), "=r"(a[mf][2]), "=r"(a[mf][3])
                             : "r"(addr));
            }
            uint32_t b[4][4];
#pragma unroll
            for (int p = 0; p < 4; p++) {
                int row = warp_n * 64 + p * 16 + ((lane >> 3) & 1) * 8 + (lane & 7);
                uint32_t addr = b_base + sw_off(row, kc);
                asm volatile("ldmatrix.sync.aligned.m8n8.x4.shared.b16 {%0,%1,%2,%3}, [%4];"
                             : "=r"(b[p][0]), "=r"(b[p][1]), "=r"(b[p][2]), "=r"(b[p][3])
                             : "r"(addr));
            }
#pragma unroll
            for (int mf = 0; mf < 2; mf++) {
#pragma unroll
                for (int nf = 0; nf < 8; nf++) {
                    int p  = nf >> 1;
                    int lo = (nf & 1);
                    asm volatile(
                        "mma.sync.aligned.m16n8k16.row.col.f32.bf16.bf16.f32 "
                        "{%0,%1,%2,%3}, {%4,%5,%6,%7}, {%8,%9}, {%0,%1,%2,%3};"
                        : "+f"(acc[mf][nf][0]), "+f"(acc[mf][nf][1]),
                          "+f"(acc[mf][nf][2]), "+f"(acc[mf][nf][3])
                        : "r"(a[mf][0]), "r"(a[mf][1]), "r"(a[mf][2]), "r"(a[mf][3]),
                          "r"(b[p][lo]), "r"(b[p][lo + 2]));
                }
            }
        }
    }

    // Epilogue ---------------------------------------------------------------
    const float INF = __uint_as_float(0x7F800000u);
    float colall[8][2], colsel[8][2];
#pragma unroll
    for (int nf = 0; nf < 8; nf++) { colall[nf][0] = colall[nf][1] = INF;
                                     colsel[nf][0] = colsel[nf][1] = INF; }

#pragma unroll
    for (int mf = 0; mf < 2; mf++) {
        int r0 = warp_m * 32 + mf * 16 + (lane >> 2);
        int r1 = r0 + 8;
        int gi0 = i0 + r0, gi1 = i0 + r1;
        int   lab0 = labels[gi0],  lab1 = labels[gi1];
        float sqi0 = g_sq[gi0],    sqi1 = g_sq[gi1];
        float dp0  = g_dap2[gi0],  dp1  = g_dap2[gi1];
        float ma0 = INF, ms0 = INF, ma1 = INF, ms1 = INF;

#pragma unroll
        for (int nf = 0; nf < 8; nf++) {
#pragma unroll
            for (int cc = 0; cc < 2; cc++) {
                int jloc = warp_n * 64 + nf * 8 + (lane & 3) * 2 + cc;
                float sqj = sqj_s[jloc];
                float dpj = dpj_s[jloc];
                int   lbj = labj_s[jloc];
                float d2a = fmaxf(sqi0 + sqj - 2.f * acc[mf][nf][cc], 0.f);
                float d2b = fmaxf(sqi1 + sqj - 2.f * acc[mf][nf][cc + 2], 0.f);
                if (lbj != lab0) {
                    ma0 = fminf(ma0, d2a);
                    if (d2a > dp0) ms0 = fminf(ms0, d2a);
                    colall[nf][cc] = fminf(colall[nf][cc], d2a);
                    if (d2a > dpj) colsel[nf][cc] = fminf(colsel[nf][cc], d2a);
                }
                if (lbj != lab1) {
                    ma1 = fminf(ma1, d2b);
                    if (d2b > dp1) ms1 = fminf(ms1, d2b);
                    colall[nf][cc] = fminf(colall[nf][cc], d2b);
                    if (d2b > dpj) colsel[nf][cc] = fminf(colsel[nf][cc], d2b);
                }
            }
        }
#pragma unroll
        for (int m = 1; m < 4; m <<= 1) {
            ma0 = fminf(ma0, __shfl_xor_sync(0xffffffffu, ma0, m));
            ms0 = fminf(ms0, __shfl_xor_sync(0xffffffffu, ms0, m));
            ma1 = fminf(ma1, __shfl_xor_sync(0xffffffffu, ma1, m));
            ms1 = fminf(ms1, __shfl_xor_sync(0xffffffffu, ms1, m));
        }
        if ((lane & 3) == 0) {
            atomicMin(&g_min_all[gi0], __float_as_uint(ma0));
            atomicMin(&g_min_sel[gi0], __float_as_uint(ms0));
            atomicMin(&g_min_all[gi1], __float_as_uint(ma1));
            atomicMin(&g_min_sel[gi1], __float_as_uint(ms1));
        }
    }

#pragma unroll
    for (int nf = 0; nf < 8; nf++)
#pragma unroll
        for (int cc = 0; cc < 2; cc++) {
#pragma unroll
            for (int m = 4; m < 32; m <<= 1) {
                colall[nf][cc] = fminf(colall[nf][cc], __shfl_xor_sync(0xffffffffu, colall[nf][cc], m));
                colsel[nf][cc] = fminf(colsel[nf][cc], __shfl_xor_sync(0xffffffffu, colsel[nf][cc], m));
            }
        }
    if (lane < 4) {
#pragma unroll
        for (int nf = 0; nf < 8; nf++)
#pragma unroll
            for (int cc = 0; cc < 2; cc++) {
                int gj = j0 + warp_n * 64 + nf * 8 + lane * 2 + cc;
                atomicMin(&g_min_all[gj], __float_as_uint(colall[nf][cc]));
                atomicMin(&g_min_sel[gj], __float_as_uint(colsel[nf][cc]));
            }
    }
}

// ---------------------------------------------------------------------------
__global__ void finalize_kernel(float* __restrict__ out) {
    __shared__ float red[256];
    float s = 0.f;
    for (int i = threadIdx.x; i < BDIM; i += 256) {
        float ms   = __uint_as_float(g_min_sel[i]);
        float ma   = __uint_as_float(g_min_all[i]);
        float dan2 = isinf(ms) ? ma : ms;
        float dan  = sqrtf(dan2);
        float l    = g_dap[i] - dan + MARGIN;
        s += (l > 0.f) ? l : 0.f;
    }
    red[threadIdx.x] = s;
    __syncthreads();
#pragma unroll
    for (int stride = 128; stride > 0; stride >>= 1) {
        if (threadIdx.x < stride) red[threadIdx.x] += red[threadIdx.x + stride];
        __syncthreads();
    }
    if (threadIdx.x == 0) out[0] = red[0] / (float)BDIM;
}

// ---------------------------------------------------------------------------
extern "C" void kernel_launch(void* const* d_in, const int* in_sizes, int n_in,
                              void* d_out, int out_size) {
    const float* anchor   = (const float*)d_in[0];
    const float* positive = (const float*)d_in[1];
    const int*   labels   = (const int*)d_in[2];
    float*       out      = (float*)d_out;

    cudaFuncSetAttribute(tile_kernel, cudaFuncAttributeMaxDynamicSharedMemorySize, DYN_SMEM);

    row_stats_kernel<<<BDIM / 16, 512>>>(anchor, positive);
    tile_kernel<<<NBLK, 256, DYN_SMEM>>>(labels);
    finalize_kernel<<<1, 256>>>(out);
}

// round 17
// speedup vs baseline: 1.2869x; 1.2869x over previous
#include <cuda_runtime.h>
#include <cuda_fp16.h>
#include <math.h>
#include <stdint.h>

#define BDIM 4096
#define DDIM 512
#define MARGIN 0.2f

#define NTILE   32
#define NBLK    (NTILE * (NTILE + 1) / 2)  // 528
#define NSTEPS  (DDIM / 32)                // 16
#define STAGE_BYTES 16384                  // A(8K) + B(8K)
#define DYN_SMEM (4 * STAGE_BYTES)         // 64KB, 4 stages

// ---------------------------------------------------------------------------
__device__ float          g_sq[BDIM];
__device__ float          g_dap[BDIM];
__device__ float          g_dap2[BDIM];
__device__ unsigned int   g_min_sel[BDIM];
__device__ unsigned int   g_min_all[BDIM];
__device__ __half         g_ahf[BDIM * DDIM];

__device__ __forceinline__ uint32_t smem_u32(const void* p) {
    uint32_t a;
    asm("{ .reg .u64 t; cvta.to.shared.u64 t, %1; cvt.u32.u64 %0, t; }" : "=r"(a) : "l"(p));
    return a;
}

// Conflict-free layout: 2 logical 64B rows per 128B line; chunk XOR line.
__device__ __forceinline__ uint32_t sw_off(int row, int kc) {
    int line  = row >> 1;
    int chunk = (((row & 1) << 2) | kc) ^ (line & 7);
    return (uint32_t)(line * 128 + chunk * 16);
}

// ---------------------------------------------------------------------------
// Kernel A: per-row stats + init minima + fp16 conversion. One warp per row.
// ---------------------------------------------------------------------------
__global__ __launch_bounds__(512)
void row_stats_kernel(const float* __restrict__ anchor,
                      const float* __restrict__ positive) {
    int warp = threadIdx.x >> 5;
    int lane = threadIdx.x & 31;
    int row  = blockIdx.x * 16 + warp;
    const float* a = anchor   + (size_t)row * DDIM;
    const float* p = positive + (size_t)row * DDIM;

    float s_sq = 0.f, s_ap = 0.f;
#pragma unroll
    for (int c = lane * 4; c < DDIM; c += 128) {
        float4 av = *reinterpret_cast<const float4*>(a + c);
        float4 pv = *reinterpret_cast<const float4*>(p + c);
        s_sq += av.x * av.x + av.y * av.y + av.z * av.z + av.w * av.w;
        float dx = av.x - pv.x, dy = av.y - pv.y, dz = av.z - pv.z, dw = av.w - pv.w;
        s_ap += dx * dx + dy * dy + dz * dz + dw * dw;
        __half2 h0 = __floats2half2_rn(av.x, av.y);
        __half2 h1 = __floats2half2_rn(av.z, av.w);
        uint2 packed = make_uint2(*reinterpret_cast<uint32_t*>(&h0),
                                  *reinterpret_cast<uint32_t*>(&h1));
        *reinterpret_cast<uint2*>(&g_ahf[(size_t)row * DDIM + c]) = packed;
    }
#pragma unroll
    for (int m = 16; m > 0; m >>= 1) {
        s_sq += __shfl_xor_sync(0xffffffffu, s_sq, m);
        s_ap += __shfl_xor_sync(0xffffffffu, s_ap, m);
    }
    if (lane == 0) {
        g_sq[row]      = s_sq;
        g_dap[row]     = s_ap;
        g_dap2[row]    = s_ap * s_ap;
        g_min_sel[row] = 0x7F800000u;
        g_min_all[row] = 0x7F800000u;
    }
}

// ---------------------------------------------------------------------------
// Kernel B: symmetric fp16 HMMA Gram tile (128x128x512), upper triangle only,
// fused row+column masked-min epilogue. 256 thr / 8 warps; warp tile 32x64.
// BK=32, 4-stage cp.async ring, one barrier/iter, fp16 accumulators.
// ---------------------------------------------------------------------------
__global__ __launch_bounds__(256, 2)
void tile_kernel(const int* __restrict__ labels) {
    extern __shared__ __align__(1024) char dsm[];
    __shared__ float sqj_s[128];
    __shared__ float dpj_s[128];
    __shared__ int   labj_s[128];

    const int tid    = threadIdx.x;
    const int wid    = tid >> 5;
    const int lane   = tid & 31;
    const int warp_m = wid & 3;
    const int warp_n = wid >> 2;

    int t = blockIdx.x;
    int bi = 0;
    {
        int rem = t;
        while (rem >= NTILE - bi) { rem -= NTILE - bi; bi++; }
        t = bi + rem;
    }
    const int bj = t;
    const int i0 = bi * 128;
    const int j0 = bj * 128;

    if (tid < 128) {
        sqj_s[tid]  = g_sq[j0 + tid];
        dpj_s[tid]  = g_dap2[j0 + tid];
        labj_s[tid] = labels[j0 + tid];
    }

    const uint32_t dsm_u = smem_u32(dsm);
    const int ld_row = tid >> 1;
    const int ld_kc0 = (tid & 1) * 2;

    auto issue_loads = [&](int stage, int k0) {
        const __half* srcA = g_ahf + (size_t)(i0 + ld_row) * DDIM + k0;
        const __half* srcB = g_ahf + (size_t)(j0 + ld_row) * DDIM + k0;
        uint32_t sbase = dsm_u + stage * STAGE_BYTES;
#pragma unroll
        for (int l = 0; l < 2; l++) {
            int kc = ld_kc0 + l;
            uint32_t off = sw_off(ld_row, kc);
            asm volatile("cp.async.cg.shared.global [%0], [%1], 16;"
                         :: "r"(sbase + off), "l"(srcA + kc * 8) : "memory");
            asm volatile("cp.async.cg.shared.global [%0], [%1], 16;"
                         :: "r"(sbase + 8192 + off), "l"(srcB + kc * 8) : "memory");
        }
        asm volatile("cp.async.commit_group;" ::: "memory");
    };

    // fp16 accumulators: 2 regs per m16n8 tile (reg0: rows r0, cols 2c/2c+1;
    // reg1: rows r0+8).
    uint32_t hacc[2][8][2];
#pragma unroll
    for (int mf = 0; mf < 2; mf++)
#pragma unroll
        for (int nf = 0; nf < 8; nf++) { hacc[mf][nf][0] = 0u; hacc[mf][nf][1] = 0u; }

    issue_loads(0, 0);
    issue_loads(1, 32);
    issue_loads(2, 64);

#pragma unroll
    for (int it = 0; it < NSTEPS; it++) {
        const int buf = it & 3;
        if (it < NSTEPS - 2)       asm volatile("cp.async.wait_group 2;" ::: "memory");
        else if (it == NSTEPS - 2) asm volatile("cp.async.wait_group 1;" ::: "memory");
        else                       asm volatile("cp.async.wait_group 0;" ::: "memory");
        __syncthreads();
        if (it + 3 < NSTEPS) issue_loads((it + 3) & 3, (it + 3) * 32);

        const uint32_t a_base = dsm_u + buf * STAGE_BYTES;
        const uint32_t b_base = a_base + 8192;
#pragma unroll
        for (int s = 0; s < 2; s++) {
            const int kc = 2 * s + (lane >> 4);
            uint32_t a[2][4];
#pragma unroll
            for (int mf = 0; mf < 2; mf++) {
                int row = warp_m * 32 + mf * 16 + ((lane >> 3) & 1) * 8 + (lane & 7);
                uint32_t addr = a_base + sw_off(row, kc);
                asm volatile("ldmatrix.sync.aligned.m8n8.x4.shared.b16 {%0,%1,%2,%3}, [%4];"
                             : "=r"(a[mf][0]), "=r"(a[mf][1]), "=r"(a[mf][2]), "=r"(a[mf][3])
                             : "r"(addr));
            }
            uint32_t b[4][4];
#pragma unroll
            for (int p = 0; p < 4; p++) {
                int row = warp_n * 64 + p * 16 + ((lane >> 3) & 1) * 8 + (lane & 7);
                uint32_t addr = b_base + sw_off(row, kc);
                asm volatile("ldmatrix.sync.aligned.m8n8.x4.shared.b16 {%0,%1,%2,%3}, [%4];"
                             : "=r"(b[p][0]), "=r"(b[p][1]), "=r"(b[p][2]), "=r"(b[p][3])
                             : "r"(addr));
            }
#pragma unroll
            for (int mf = 0; mf < 2; mf++) {
#pragma unroll
                for (int nf = 0; nf < 8; nf++) {
                    int p  = nf >> 1;
                    int lo = (nf & 1);
                    asm volatile(
                        "mma.sync.aligned.m16n8k16.row.col.f16.f16.f16.f16 "
                        "{%0,%1}, {%2,%3,%4,%5}, {%6,%7}, {%0,%1};"
                        : "+r"(hacc[mf][nf][0]), "+r"(hacc[mf][nf][1])
                        : "r"(a[mf][0]), "r"(a[mf][1]), "r"(a[mf][2]), "r"(a[mf][3]),
                          "r"(b[p][lo]), "r"(b[p][lo + 2]));
                }
            }
        }
    }

    // Epilogue ---------------------------------------------------------------
    const float INF = __uint_as_float(0x7F800000u);
    float colall[8][2], colsel[8][2];
#pragma unroll
    for (int nf = 0; nf < 8; nf++) { colall[nf][0] = colall[nf][1] = INF;
                                     colsel[nf][0] = colsel[nf][1] = INF; }

#pragma unroll
    for (int mf = 0; mf < 2; mf++) {
        int r0 = warp_m * 32 + mf * 16 + (lane >> 2);
        int r1 = r0 + 8;
        int gi0 = i0 + r0, gi1 = i0 + r1;
        int   lab0 = labels[gi0],  lab1 = labels[gi1];
        float sqi0 = g_sq[gi0],    sqi1 = g_sq[gi1];
        float dp0  = g_dap2[gi0],  dp1  = g_dap2[gi1];
        float ma0 = INF, ms0 = INF, ma1 = INF, ms1 = INF;

#pragma unroll
        for (int nf = 0; nf < 8; nf++) {
            float2 lo = __half22float2(*reinterpret_cast<__half2*>(&hacc[mf][nf][0]));
            float2 hi = __half22float2(*reinterpret_cast<__half2*>(&hacc[mf][nf][1]));
            float accv[2][2] = { { lo.x, lo.y }, { hi.x, hi.y } };
#pragma unroll
            for (int cc = 0; cc < 2; cc++) {
                int jloc = warp_n * 64 + nf * 8 + (lane & 3) * 2 + cc;
                float sqj = sqj_s[jloc];
                float dpj = dpj_s[jloc];
                int   lbj = labj_s[jloc];
                float d2a = fmaxf(sqi0 + sqj - 2.f * accv[0][cc], 0.f);
                float d2b = fmaxf(sqi1 + sqj - 2.f * accv[1][cc], 0.f);
                if (lbj != lab0) {
                    ma0 = fminf(ma0, d2a);
                    if (d2a > dp0) ms0 = fminf(ms0, d2a);
                    colall[nf][cc] = fminf(colall[nf][cc], d2a);
                    if (d2a > dpj) colsel[nf][cc] = fminf(colsel[nf][cc], d2a);
                }
                if (lbj != lab1) {
                    ma1 = fminf(ma1, d2b);
                    if (d2b > dp1) ms1 = fminf(ms1, d2b);
                    colall[nf][cc] = fminf(colall[nf][cc], d2b);
                    if (d2b > dpj) colsel[nf][cc] = fminf(colsel[nf][cc], d2b);
                }
            }
        }
#pragma unroll
        for (int m = 1; m < 4; m <<= 1) {
            ma0 = fminf(ma0, __shfl_xor_sync(0xffffffffu, ma0, m));
            ms0 = fminf(ms0, __shfl_xor_sync(0xffffffffu, ms0, m));
            ma1 = fminf(ma1, __shfl_xor_sync(0xffffffffu, ma1, m));
            ms1 = fminf(ms1, __shfl_xor_sync(0xffffffffu, ms1, m));
        }
        if ((lane & 3) == 0) {
            atomicMin(&g_min_all[gi0], __float_as_uint(ma0));
            atomicMin(&g_min_sel[gi0], __float_as_uint(ms0));
            atomicMin(&g_min_all[gi1], __float_as_uint(ma1));
            atomicMin(&g_min_sel[gi1], __float_as_uint(ms1));
        }
    }

#pragma unroll
    for (int nf = 0; nf < 8; nf++)
#pragma unroll
        for (int cc = 0; cc < 2; cc++) {
#pragma unroll
            for (int m = 4; m < 32; m <<= 1) {
                colall[nf][cc] = fminf(colall[nf][cc], __shfl_xor_sync(0xffffffffu, colall[nf][cc], m));
                colsel[nf][cc] = fminf(colsel[nf][cc], __shfl_xor_sync(0xffffffffu, colsel[nf][cc], m));
            }
        }
    if (lane < 4) {
#pragma unroll
        for (int nf = 0; nf < 8; nf++)
#pragma unroll
            for (int cc = 0; cc < 2; cc++) {
                int gj = j0 + warp_n * 64 + nf * 8 + lane * 2 + cc;
                atomicMin(&g_min_all[gj], __float_as_uint(colall[nf][cc]));
                atomicMin(&g_min_sel[gj], __float_as_uint(colsel[nf][cc]));
            }
    }
}

// ---------------------------------------------------------------------------
__global__ void finalize_kernel(float* __restrict__ out) {
    __shared__ float red[256];
    float s = 0.f;
    for (int i = threadIdx.x; i < BDIM; i += 256) {
        float ms   = __uint_as_float(g_min_sel[i]);
        float ma   = __uint_as_float(g_min_all[i]);
        float dan2 = isinf(ms) ? ma : ms;
        float dan  = sqrtf(dan2);
        float l    = g_dap[i] - dan + MARGIN;
        s += (l > 0.f) ? l : 0.f;
    }
    red[threadIdx.x] = s;
    __syncthreads();
#pragma unroll
    for (int stride = 128; stride > 0; stride >>= 1) {
        if (threadIdx.x < stride) red[threadIdx.x] += red[threadIdx.x + stride];
        __syncthreads();
    }
    if (threadIdx.x == 0) out[0] = red[0] / (float)BDIM;
}

// ---------------------------------------------------------------------------
extern "C" void kernel_launch(void* const* d_in, const int* in_sizes, int n_in,
                              void* d_out, int out_size) {
    const float* anchor   = (const float*)d_in[0];
    const float* positive = (const float*)d_in[1];
    const int*   labels   = (const int*)d_in[2];
    float*       out      = (float*)d_out;

    cudaFuncSetAttribute(tile_kernel, cudaFuncAttributeMaxDynamicSharedMemorySize, DYN_SMEM);

    row_stats_kernel<<<BDIM / 16, 512>>>(anchor, positive);
    tile_kernel<<<NBLK, 256, DYN_SMEM>>>(labels);
    finalize_kernel<<<1, 256>>>(out);
}